// round 3
// baseline (speedup 1.0000x reference)
#include <cuda_runtime.h>

#define NVOX 524288
#define BVOX 262144
#define NBLK 2048

__device__ float4 g_img4[NVOX];
__device__ int    g_lbl[NVOX];
__device__ float  g_partial[NBLK];
__device__ int    g_is64;

// Detect whether labels buffer is int64 (high 32-bit words all zero) or int32.
__global__ void detect_k(const unsigned int* __restrict__ lab) {
    __shared__ unsigned int sh[256];
    unsigned int a = 0u;
    for (int i = threadIdx.x; i < BVOX; i += 256) a |= lab[2 * i + 1];
    sh[threadIdx.x] = a;
    __syncthreads();
    for (int st = 128; st; st >>= 1) {
        if (threadIdx.x < st) sh[threadIdx.x] |= sh[threadIdx.x + st];
        __syncthreads();
    }
    if (threadIdx.x == 0) g_is64 = (sh[0] == 0u) ? 1 : 0;
}

// Transpose images [B,C,D,H,W] -> per-voxel float4; labels -> int.
__global__ void __launch_bounds__(256) prep_k(const float* __restrict__ images,
                                              const void* __restrict__ labels) {
    int i = blockIdx.x * 256 + threadIdx.x;
    int b = i >> 18;
    int s = i & (BVOX - 1);
    const float* p = images + (size_t)b * (4 * BVOX) + s;
    float4 v;
    v.x = p[0];
    v.y = p[BVOX];
    v.z = p[2 * BVOX];
    v.w = p[3 * BVOX];
    g_img4[i] = v;
    int lbl;
    if (g_is64) lbl = (int)((const long long*)labels)[i];
    else        lbl = ((const int*)labels)[i];
    g_lbl[i] = lbl;
}

__global__ void __launch_bounds__(256) main_k(const float* __restrict__ inputs) {
    int tid = blockIdx.x * 256 + threadIdx.x;
    int b = tid >> 18;
    int s = tid & (BVOX - 1);
    int x = s & 63, y = (s >> 6) & 63, z = s >> 12;

    const float* ip = inputs + (size_t)b * (4 * BVOX) + s;
    float i0 = ip[0], i1 = ip[BVOX], i2 = ip[2 * BVOX], i3 = ip[3 * BVOX];
    float mx = fmaxf(fmaxf(i0, i1), fmaxf(i2, i3));
    float lse = mx + __logf(__expf(i0 - mx) + __expf(i1 - mx) +
                            __expf(i2 - mx) + __expf(i3 - mx));

    float4 c4 = g_img4[tid];
    int zc[3] = { z > 0 ? z - 1 : 0, z, z < 63 ? z + 1 : 63 };
    int yc[3] = { y > 0 ? y - 1 : 0, y, y < 63 ? y + 1 : 63 };
    int xc[3] = { x > 0 ? x - 1 : 0, x, x < 63 ? x + 1 : 63 };
    int bb = b << 18;

    float S = 0.f, acc = 0.f;
    int lc = 0;

    #pragma unroll
    for (int iz = 0; iz < 3; iz++) {
        #pragma unroll
        for (int iy = 0; iy < 3; iy++) {
            int rb = bb + (zc[iz] << 12) + (yc[iy] << 6);
            #pragma unroll
            for (int ix = 0; ix < 3; ix++) {
                int ni = rb + xc[ix];
                float4 n4 = g_img4[ni];
                int lbl = g_lbl[ni];
                if (iz == 1 && iy == 1 && ix == 1) lc = lbl;
                float df = fmaxf(fmaxf(n4.x - c4.x, n4.y - c4.y),
                                 fmaxf(n4.z - c4.z, n4.w - c4.w));
                // e = exp(-df*df/2), degree-5 Taylor at x=0.5 (x=df^2 in [0,1))
                float u = fmaf(df, df, -0.5f);
                float e = fmaf(-0.00020281270f, u, 0.0020281270f);
                e = fmaf(e, u, -0.016225016f);
                e = fmaf(e, u,  0.097350098f);
                e = fmaf(e, u, -0.38940039f);
                e = fmaf(e, u,  0.77880078f);
                const int d2 = (iz - 1) * (iz - 1) + (iy - 1) * (iy - 1)
                             + (ix - 1) * (ix - 1);
                const float dw = (d2 == 0) ? 1.0f
                               : (d2 == 1) ? 0.60653066f
                               : (d2 == 2) ? 0.36787944f
                               :             0.22313016f;
                float wgt = dw * e;
                S += wgt;
                float v01 = (lbl & 1) ? i1 : i0;
                float v23 = (lbl & 1) ? i3 : i2;
                float vi  = (lbl & 2) ? v23 : v01;
                acc = fmaf(wgt, vi, acc);
            }
        }
    }

    float v01 = (lc & 1) ? i1 : i0;
    float v23 = (lc & 1) ? i3 : i2;
    float vc  = (lc & 2) ? v23 : v01;
    // final weights: f_i = w_i/(2(S-1)) for i != center, f_ctr = (S-1)/(2(S-1));
    // loss = lse - (acc - vc + (S-1)*vc) / (2(S-1))
    float num = acc + (S - 2.0f) * vc;
    float loss = lse - num / (2.0f * (S - 1.0f));

    // block reduction (deterministic)
    #pragma unroll
    for (int o = 16; o; o >>= 1) loss += __shfl_down_sync(0xffffffffu, loss, o);
    __shared__ float sw[8];
    int lane = threadIdx.x & 31, wrp = threadIdx.x >> 5;
    if (lane == 0) sw[wrp] = loss;
    __syncthreads();
    if (threadIdx.x == 0) {
        float t = 0.f;
        #pragma unroll
        for (int k = 0; k < 8; k++) t += sw[k];
        g_partial[blockIdx.x] = t;
    }
}

__global__ void final_k(float* __restrict__ out) {
    __shared__ float sh[256];
    float a = 0.f;
    for (int i = threadIdx.x; i < NBLK; i += 256) a += g_partial[i];
    sh[threadIdx.x] = a;
    __syncthreads();
    for (int st = 128; st; st >>= 1) {
        if (threadIdx.x < st) sh[threadIdx.x] += sh[threadIdx.x + st];
        __syncthreads();
    }
    if (threadIdx.x == 0) out[0] = sh[0] * (1.0f / 524288.0f);
}

extern "C" void kernel_launch(void* const* d_in, const int* in_sizes, int n_in,
                              void* d_out, int out_size) {
    // Map inputs robustly: labels is the buffer with 524288 elements;
    // of the remaining two (each 2097152), first is inputs, second is images
    // (reference signature order: inputs, labels, images).
    int li = 1;
    for (int i = 0; i < n_in; i++) if (in_sizes[i] == NVOX) li = i;
    int rem[2], r = 0;
    for (int i = 0; i < n_in && r < 2; i++) if (i != li) rem[r++] = i;

    const float* inputs = (const float*)d_in[rem[0]];
    const void*  labels = d_in[li];
    const float* images = (const float*)d_in[rem[1]];

    detect_k<<<1, 256>>>((const unsigned int*)labels);
    prep_k<<<NBLK, 256>>>(images, labels);
    main_k<<<NBLK, 256>>>(inputs);
    final_k<<<1, 256>>>((float*)d_out);
}

// round 4
// speedup vs baseline: 1.0298x; 1.0298x over previous
#include <cuda_runtime.h>

#define NVOX 524288
#define BVOX 262144
#define NBLK 2048

__device__ float4 g_img4[NVOX];
__device__ int    g_lbl[NVOX];
__device__ float  g_partial[NBLK];
__device__ int    g_is64;

// Detect whether labels buffer is int64 (high 32-bit words all zero) or int32.
__global__ void detect_k(const unsigned int* __restrict__ lab) {
    __shared__ unsigned int sh[256];
    unsigned int a = 0u;
    for (int i = threadIdx.x; i < BVOX; i += 256) a |= lab[2 * i + 1];
    sh[threadIdx.x] = a;
    __syncthreads();
    for (int st = 128; st; st >>= 1) {
        if (threadIdx.x < st) sh[threadIdx.x] |= sh[threadIdx.x + st];
        __syncthreads();
    }
    if (threadIdx.x == 0) g_is64 = (sh[0] == 0u) ? 1 : 0;
}

// Transpose images [B,C,D,H,W] -> per-voxel float4; labels -> int.
__global__ void __launch_bounds__(256) prep_k(const float* __restrict__ images,
                                              const void* __restrict__ labels) {
    int i = blockIdx.x * 256 + threadIdx.x;
    int b = i >> 18;
    int s = i & (BVOX - 1);
    const float* p = images + (size_t)b * (4 * BVOX) + s;
    float4 v;
    v.x = p[0];
    v.y = p[BVOX];
    v.z = p[2 * BVOX];
    v.w = p[3 * BVOX];
    g_img4[i] = v;
    int lbl;
    if (g_is64) lbl = (int)((const long long*)labels)[i];
    else        lbl = ((const int*)labels)[i];
    g_lbl[i] = lbl;
}

__global__ void __launch_bounds__(256) main_k(const float* __restrict__ inputs) {
    int tid = blockIdx.x * 256 + threadIdx.x;
    int b = tid >> 18;
    int s = tid & (BVOX - 1);
    int x = s & 63, y = (s >> 6) & 63, z = s >> 12;

    const float* ip = inputs + (size_t)b * (4 * BVOX) + s;
    float i0 = ip[0], i1 = ip[BVOX], i2 = ip[2 * BVOX], i3 = ip[3 * BVOX];
    float mx = fmaxf(fmaxf(i0, i1), fmaxf(i2, i3));
    float lse = mx + __logf(__expf(i0 - mx) + __expf(i1 - mx) +
                            __expf(i2 - mx) + __expf(i3 - mx));

    float4 c4 = g_img4[tid];
    int zc[3] = { z > 0 ? z - 1 : 0, z, z < 63 ? z + 1 : 63 };
    int yc[3] = { y > 0 ? y - 1 : 0, y, y < 63 ? y + 1 : 63 };
    int xc[3] = { x > 0 ? x - 1 : 0, x, x < 63 ? x + 1 : 63 };
    int bb = b << 18;

    float S = 0.f, acc = 0.f;
    int lc = 0;

    #pragma unroll
    for (int iz = 0; iz < 3; iz++) {
        #pragma unroll
        for (int iy = 0; iy < 3; iy++) {
            int rb = bb + (zc[iz] << 12) + (yc[iy] << 6);
            #pragma unroll
            for (int ix = 0; ix < 3; ix++) {
                int ni = rb + xc[ix];
                float4 n4 = g_img4[ni];
                int lbl = g_lbl[ni];
                if (iz == 1 && iy == 1 && ix == 1) lc = lbl;
                float df = fmaxf(fmaxf(n4.x - c4.x, n4.y - c4.y),
                                 fmaxf(n4.z - c4.z, n4.w - c4.w));
                // e = exp(-df*df/2), degree-5 Taylor at x=0.5 (x=df^2 in [0,1))
                float u = fmaf(df, df, -0.5f);
                float e = fmaf(-0.00020281270f, u, 0.0020281270f);
                e = fmaf(e, u, -0.016225016f);
                e = fmaf(e, u,  0.097350098f);
                e = fmaf(e, u, -0.38940039f);
                e = fmaf(e, u,  0.77880078f);
                const int d2 = (iz - 1) * (iz - 1) + (iy - 1) * (iy - 1)
                             + (ix - 1) * (ix - 1);
                const float dw = (d2 == 0) ? 1.0f
                               : (d2 == 1) ? 0.60653066f
                               : (d2 == 2) ? 0.36787944f
                               :             0.22313016f;
                float wgt = dw * e;
                S += wgt;
                float v01 = (lbl & 1) ? i1 : i0;
                float v23 = (lbl & 1) ? i3 : i2;
                float vi  = (lbl & 2) ? v23 : v01;
                acc = fmaf(wgt, vi, acc);
            }
        }
    }

    float v01 = (lc & 1) ? i1 : i0;
    float v23 = (lc & 1) ? i3 : i2;
    float vc  = (lc & 2) ? v23 : v01;
    // final weights: f_i = w_i/(2(S-1)) for i != center, f_ctr = (S-1)/(2(S-1));
    // loss = lse - (acc - vc + (S-1)*vc) / (2(S-1))
    float num = acc + (S - 2.0f) * vc;
    float loss = lse - num / (2.0f * (S - 1.0f));

    // block reduction (deterministic)
    #pragma unroll
    for (int o = 16; o; o >>= 1) loss += __shfl_down_sync(0xffffffffu, loss, o);
    __shared__ float sw[8];
    int lane = threadIdx.x & 31, wrp = threadIdx.x >> 5;
    if (lane == 0) sw[wrp] = loss;
    __syncthreads();
    if (threadIdx.x == 0) {
        float t = 0.f;
        #pragma unroll
        for (int k = 0; k < 8; k++) t += sw[k];
        g_partial[blockIdx.x] = t;
    }
}

__global__ void final_k(float* __restrict__ out) {
    __shared__ float sh[256];
    float a = 0.f;
    for (int i = threadIdx.x; i < NBLK; i += 256) a += g_partial[i];
    sh[threadIdx.x] = a;
    __syncthreads();
    for (int st = 128; st; st >>= 1) {
        if (threadIdx.x < st) sh[threadIdx.x] += sh[threadIdx.x + st];
        __syncthreads();
    }
    if (threadIdx.x == 0) out[0] = sh[0] * (1.0f / 524288.0f);
}

extern "C" void kernel_launch(void* const* d_in, const int* in_sizes, int n_in,
                              void* d_out, int out_size) {
    // Map inputs robustly: labels is the buffer with 524288 elements;
    // of the remaining two (each 2097152), first is inputs, second is images
    // (reference signature order: inputs, labels, images).
    int li = 1;
    for (int i = 0; i < n_in; i++) if (in_sizes[i] == NVOX) li = i;
    int rem[2], r = 0;
    for (int i = 0; i < n_in && r < 2; i++) if (i != li) rem[r++] = i;

    const float* inputs = (const float*)d_in[rem[0]];
    const void*  labels = d_in[li];
    const float* images = (const float*)d_in[rem[1]];

    detect_k<<<1, 256>>>((const unsigned int*)labels);
    prep_k<<<NBLK, 256>>>(images, labels);
    main_k<<<NBLK, 256>>>(inputs);
    final_k<<<1, 256>>>((float*)d_out);
}